// round 1
// baseline (speedup 1.0000x reference)
#include <cuda_runtime.h>
#include <math.h>

// YOLOv5-style loss, fully fused scatter-free formulation.
// Output: [loss, lbox, lobj, lcls]  (4 floats)

#define NA_   3
#define NC_   80
#define CH_   85
#define EPS_  1e-7f

// ---------------- device scratch (no allocations allowed) ----------------
__device__ float g_box[3];
__device__ float g_cls[3];
__device__ float g_corr[3];
__device__ float g_sp[3];
__device__ int   g_nv[3];

#define MAX_BS 32
#define CELLS_PER_B (NA_*(80*80 + 40*40 + 20*20))   // 25200
__device__ int g_winner[MAX_BS * CELLS_PER_B];      // last-wins scatter resolution

#define MAX_ENT (5 * NA_ * 4096)
__device__ float g_iou_s[MAX_ENT];
__device__ float g_x4_s[MAX_ENT];
__device__ int   g_cell_s[MAX_ENT];

// ---------------- helpers ----------------
__device__ __forceinline__ float sigmoidf_(float x) {
    return 1.0f / (1.0f + expf(-x));
}

__device__ __forceinline__ float softplus_bce0(float x) {
    // bce(x, 0) = max(x,0) + log1p(exp(-|x|))
    return fmaxf(x, 0.0f) + log1pf(expf(-fabsf(x)));
}

__device__ __forceinline__ float ciou_(float px, float py, float pw, float ph,
                                       float tx, float ty, float tw, float th) {
    float b1x1 = px - pw * 0.5f, b1x2 = px + pw * 0.5f;
    float b1y1 = py - ph * 0.5f, b1y2 = py + ph * 0.5f;
    float b2x1 = tx - tw * 0.5f, b2x2 = tx + tw * 0.5f;
    float b2y1 = ty - th * 0.5f, b2y2 = ty + th * 0.5f;

    float iw = fmaxf(fminf(b1x2, b2x2) - fmaxf(b1x1, b2x1), 0.0f);
    float ih = fmaxf(fminf(b1y2, b2y2) - fmaxf(b1y1, b2y1), 0.0f);
    float inter = iw * ih;

    float w1 = b1x2 - b1x1, h1 = b1y2 - b1y1 + EPS_;
    float w2 = b2x2 - b2x1, h2 = b2y2 - b2y1 + EPS_;
    float uni = w1 * h1 + w2 * h2 - inter + EPS_;
    float iou = inter / uni;

    float cw = fmaxf(b1x2, b2x2) - fminf(b1x1, b2x1);
    float ch = fmaxf(b1y2, b2y2) - fminf(b1y1, b2y1);
    float c2 = cw * cw + ch * ch + EPS_;

    float dx = (b2x1 + b2x2 - b1x1 - b1x2);
    float dy = (b2y1 + b2y2 - b1y1 - b1y2);
    float rho2 = (dx * dx + dy * dy) * 0.25f;

    float dv = atanf(w2 / h2) - atanf(w1 / h1);
    float v = (4.0f / (float)(M_PI * M_PI)) * dv * dv;
    float alpha = v / (v - iou + (1.0f + EPS_));

    return iou - (rho2 / c2 + v * alpha);
}

// ---------------- kernels ----------------
__global__ void k_reset(int nwin) {
    int i = blockIdx.x * blockDim.x + threadIdx.x;
    if (i < nwin) g_winner[i] = 0;
    if (i < 3) {
        g_box[i] = 0.0f; g_cls[i] = 0.0f; g_corr[i] = 0.0f;
        g_sp[i] = 0.0f;  g_nv[i] = 0;
    }
}

// One warp per candidate entry e = o*M + (a*nt + n), o in [0,5).
__global__ void k_passA(const float* __restrict__ pi,
                        const float* __restrict__ tg,
                        const float* __restrict__ anc,
                        int nt, int H, int W, int lvl, int woff) {
    int warp = (blockIdx.x * blockDim.x + threadIdx.x) >> 5;
    int lane = threadIdx.x & 31;
    int M = NA_ * nt;
    int E = 5 * M;
    if (warp >= E) return;

    int o = warp / M;
    int m = warp - o * M;
    int a = m / nt;
    int n = m - a * nt;

    float gx = tg[n * 6 + 2] * (float)W;
    float gy = tg[n * 6 + 3] * (float)H;
    float gw = tg[n * 6 + 4] * (float)W;
    float gh = tg[n * 6 + 5] * (float)H;

    float aw = anc[(lvl * NA_ + a) * 2 + 0];
    float ah = anc[(lvl * NA_ + a) * 2 + 1];

    float rw = gw / aw, rh = gh / ah;
    float mr = fmaxf(fmaxf(rw, 1.0f / rw), fmaxf(rh, 1.0f / rh));
    bool m0 = mr < 4.0f;

    bool jmo;
    float offx = 0.0f, offy = 0.0f;
    switch (o) {
        case 0: jmo = true; break;
        case 1: jmo = (fmodf(gx, 1.0f) < 0.5f) && (gx > 1.0f); offx = 0.5f; break;
        case 2: jmo = (fmodf(gy, 1.0f) < 0.5f) && (gy > 1.0f); offy = 0.5f; break;
        case 3: { float gxi = (float)W - gx;
                  jmo = (fmodf(gxi, 1.0f) < 0.5f) && (gxi > 1.0f); offx = -0.5f; } break;
        default:{ float gyi = (float)H - gy;
                  jmo = (fmodf(gyi, 1.0f) < 0.5f) && (gyi > 1.0f); offy = -0.5f; } break;
    }

    bool masked = jmo && m0;
    if (!masked) {
        if (lane == 0) g_cell_s[warp] = -1;
        return;
    }

    int b = (int)tg[n * 6 + 0];
    int c = (int)tg[n * 6 + 1];

    int gi = (int)truncf(gx - offx); gi = min(max(gi, 0), W - 1);
    int gj = (int)truncf(gy - offy); gj = min(max(gj, 0), H - 1);

    const float* row = pi + (size_t)((((b * NA_ + a) * H + gj) * W + gi)) * CH_;

    // class BCE across the warp
    float csum = 0.0f;
    for (int j = lane; j < NC_; j += 32) {
        float x = row[5 + j];
        float y = (j == c) ? 1.0f : 0.0f;
        csum += fmaxf(x, 0.0f) - x * y + log1pf(expf(-fabsf(x)));
    }
    #pragma unroll
    for (int s = 16; s; s >>= 1)
        csum += __shfl_down_sync(0xffffffffu, csum, s);

    if (lane == 0) {
        float p0 = row[0], p1 = row[1], p2 = row[2], p3 = row[3], p4 = row[4];
        float px = sigmoidf_(p0) * 2.0f - 0.5f;
        float py = sigmoidf_(p1) * 2.0f - 0.5f;
        float sw = sigmoidf_(p2) * 2.0f; float pw = sw * sw * aw;
        float sh = sigmoidf_(p3) * 2.0f; float ph = sh * sh * ah;

        float tbx = gx - (float)gi;
        float tby = gy - (float)gj;

        float iou = ciou_(px, py, pw, ph, tbx, tby, gw, gh);

        atomicAdd(&g_box[lvl], 1.0f - iou);
        atomicAdd(&g_cls[lvl], csum);
        atomicAdd(&g_nv[lvl], 1);

        int cell = woff + (((b * NA_ + a) * H + gj) * W + gi);
        atomicMax(&g_winner[cell], warp + 1);   // last-update-wins (highest entry index)
        g_iou_s[warp]  = iou;
        g_x4_s[warp]   = p4;
        g_cell_s[warp] = cell;
    }
}

// winner entries contribute the -x*t correction to lobj
__global__ void k_passB(int E, int lvl) {
    int e = blockIdx.x * blockDim.x + threadIdx.x;
    if (e >= E) return;
    int cell = g_cell_s[e];
    if (cell < 0) return;
    if (g_winner[cell] != e + 1) return;
    float t = fmaxf(g_iou_s[e], 0.0f);   // obj_val = 1-GR + GR*clip(iou,0), GR=1
    atomicAdd(&g_corr[lvl], g_x4_s[e] * t);
}

// sum softplus over the obj channel (channel 4 of 85)
__global__ void k_objsum(const float* __restrict__ pi, int ncells, int lvl) {
    __shared__ float sh[256];
    int tid = threadIdx.x;
    float s = 0.0f;
    for (long long i = (long long)blockIdx.x * blockDim.x + tid; i < ncells;
         i += (long long)gridDim.x * blockDim.x) {
        float x = pi[i * CH_ + 4];
        s += softplus_bce0(x);
    }
    sh[tid] = s;
    __syncthreads();
    for (int st = 128; st; st >>= 1) {
        if (tid < st) sh[tid] += sh[tid + st];
        __syncthreads();
    }
    if (tid == 0) atomicAdd(&g_sp[lvl], sh[0]);
}

__global__ void k_finalize(float* __restrict__ out, int bs, int n0, int n1, int n2) {
    float lbox = 0.0f, lcls = 0.0f, lobj = 0.0f;
    int nn[3] = {n0, n1, n2};
    #pragma unroll
    for (int i = 0; i < 3; i++) {
        float nv = fmaxf((float)g_nv[i], 1.0f);
        lbox += g_box[i] / nv;
        lcls += g_cls[i] / (nv * (float)NC_);
        lobj += (g_sp[i] - g_corr[i]) / (float)nn[i];
    }
    lbox *= 0.05f;   // BOX_GAIN
    lcls *= 0.5f;    // CLS_GAIN
    // OBJ_GAIN = 1.0 applied twice -> no-op
    float loss = (lbox + lobj + lcls) * (float)bs;
    out[0] = loss;
    out[1] = lbox;
    out[2] = lobj;
    out[3] = lcls;
}

// ---------------- launch ----------------
extern "C" void kernel_launch(void* const* d_in, const int* in_sizes, int n_in,
                              void* d_out, int out_size) {
    const float* p0  = (const float*)d_in[0];
    const float* p1  = (const float*)d_in[1];
    const float* p2  = (const float*)d_in[2];
    const float* tg  = (const float*)d_in[3];
    const float* anc = (const float*)d_in[4];
    float* out = (float*)d_out;

    int bs = in_sizes[0] / (NA_ * 80 * 80 * CH_);
    int nt = in_sizes[3] / 6;

    const int Hs[3] = {80, 40, 20};
    const float* ps[3] = {p0, p1, p2};

    int woff[3];
    woff[0] = 0;
    woff[1] = bs * NA_ * 80 * 80;
    woff[2] = woff[1] + bs * NA_ * 40 * 40;
    int nwin = woff[2] + bs * NA_ * 20 * 20;

    int E = 5 * NA_ * nt;

    k_reset<<<(nwin + 255) / 256, 256>>>(nwin);

    for (int lvl = 0; lvl < 3; lvl++) {
        int H = Hs[lvl];
        int blocksA = (E * 32 + 255) / 256;
        k_passA<<<blocksA, 256>>>(ps[lvl], tg, anc, nt, H, H, lvl, woff[lvl]);
        k_passB<<<(E + 255) / 256, 256>>>(E, lvl);
    }

    for (int lvl = 0; lvl < 3; lvl++) {
        int H = Hs[lvl];
        int ncells = bs * NA_ * H * H;
        int blocks = (ncells + 255) / 256;
        if (blocks > 2048) blocks = 2048;
        k_objsum<<<blocks, 256>>>(ps[lvl], ncells, lvl);
    }

    k_finalize<<<1, 1>>>(out, bs,
                         bs * NA_ * 80 * 80,
                         bs * NA_ * 40 * 40,
                         bs * NA_ * 20 * 20);
}

// round 2
// speedup vs baseline: 1.4558x; 1.4558x over previous
#include <cuda_runtime.h>
#include <math.h>

// YOLOv5-style loss, fused scatter-free formulation.
// Output: [loss, lbox, lobj, lcls]  (4 floats)

#define NA_   3
#define NC_   80
#define CH_   85
#define EPS_  1e-7f

// ---------------- device scratch (no allocations allowed) ----------------
__device__ float g_box[3];
__device__ float g_cls[3];
__device__ float g_corr;     // weighted sum: x4 * obj_val / n_lvl
__device__ float g_sp;       // weighted sum: softplus(x4) / n_lvl
__device__ int   g_nv[3];

#define MAX_BS 32
#define CELLS_PER_B (NA_*(80*80 + 40*40 + 20*20))   // 25200
__device__ int g_winner[MAX_BS * CELLS_PER_B];      // last-wins scatter resolution

#define MAX_ENT (3 * 5 * NA_ * 4096)
__device__ float g_iou_s[MAX_ENT];
__device__ float g_x4_s[MAX_ENT];
__device__ int   g_cell_s[MAX_ENT];

// ---------------- helpers ----------------
__device__ __forceinline__ float sigmoidf_(float x) {
    return 1.0f / (1.0f + __expf(-x));
}

__device__ __forceinline__ float softplus_bce0(float x) {
    // bce(x, 0) = max(x,0) + log1p(exp(-|x|))
    return fmaxf(x, 0.0f) + log1pf(__expf(-fabsf(x)));
}

__device__ __forceinline__ float ciou_(float px, float py, float pw, float ph,
                                       float tx, float ty, float tw, float th) {
    float b1x1 = px - pw * 0.5f, b1x2 = px + pw * 0.5f;
    float b1y1 = py - ph * 0.5f, b1y2 = py + ph * 0.5f;
    float b2x1 = tx - tw * 0.5f, b2x2 = tx + tw * 0.5f;
    float b2y1 = ty - th * 0.5f, b2y2 = ty + th * 0.5f;

    float iw = fmaxf(fminf(b1x2, b2x2) - fmaxf(b1x1, b2x1), 0.0f);
    float ih = fmaxf(fminf(b1y2, b2y2) - fmaxf(b1y1, b2y1), 0.0f);
    float inter = iw * ih;

    float w1 = b1x2 - b1x1, h1 = b1y2 - b1y1 + EPS_;
    float w2 = b2x2 - b2x1, h2 = b2y2 - b2y1 + EPS_;
    float uni = w1 * h1 + w2 * h2 - inter + EPS_;
    float iou = inter / uni;

    float cw = fmaxf(b1x2, b2x2) - fminf(b1x1, b2x1);
    float ch = fmaxf(b1y2, b2y2) - fminf(b1y1, b2y1);
    float c2 = cw * cw + ch * ch + EPS_;

    float dx = (b2x1 + b2x2 - b1x1 - b1x2);
    float dy = (b2y1 + b2y2 - b1y1 - b1y2);
    float rho2 = (dx * dx + dy * dy) * 0.25f;

    float dv = atanf(w2 / h2) - atanf(w1 / h1);
    float v = (4.0f / (float)(M_PI * M_PI)) * dv * dv;
    float alpha = v / (v - iou + (1.0f + EPS_));

    return iou - (rho2 / c2 + v * alpha);
}

// ---------------- kernels ----------------
__global__ void k_reset(int nwin) {
    int i = blockIdx.x * blockDim.x + threadIdx.x;
    if (i < nwin) g_winner[i] = 0;
    if (i < 3) { g_box[i] = 0.0f; g_cls[i] = 0.0f; g_nv[i] = 0; }
    if (i == 0) { g_corr = 0.0f; g_sp = 0.0f; }
}

// Fused: blocks [0, BA) -> passA over all 3 levels (one warp per candidate);
//        blocks [BA, BA+BOBJ) -> weighted softplus sweep over obj channel of all levels.
__global__ void k_main(const float* __restrict__ p0,
                       const float* __restrict__ p1,
                       const float* __restrict__ p2,
                       const float* __restrict__ tg,
                       const float* __restrict__ anc,
                       int nt, int bs, int BA, int BOBJ) {
    int M = NA_ * nt;
    int Elvl = 5 * M;

    if ((int)blockIdx.x < BA) {
        // ---------------- passA ----------------
        int warp = (blockIdx.x * blockDim.x + threadIdx.x) >> 5;
        int lane = threadIdx.x & 31;
        int Etot = 3 * Elvl;
        if (warp >= Etot) return;

        int lvl = warp / Elvl;
        int ein = warp - lvl * Elvl;
        int o = ein / M;
        int m = ein - o * M;
        int a = m / nt;
        int n = m - a * nt;

        int H = 80 >> lvl;
        int W = H;
        const float* pi = (lvl == 0) ? p0 : ((lvl == 1) ? p1 : p2);
        int woff = (lvl == 0) ? 0
                 : ((lvl == 1) ? bs * NA_ * 6400
                               : bs * NA_ * (6400 + 1600));

        float gx = tg[n * 6 + 2] * (float)W;
        float gy = tg[n * 6 + 3] * (float)H;
        float gw = tg[n * 6 + 4] * (float)W;
        float gh = tg[n * 6 + 5] * (float)H;

        float aw = anc[(lvl * NA_ + a) * 2 + 0];
        float ah = anc[(lvl * NA_ + a) * 2 + 1];

        float rw = gw / aw, rh = gh / ah;
        float mr = fmaxf(fmaxf(rw, 1.0f / rw), fmaxf(rh, 1.0f / rh));
        bool m0 = mr < 4.0f;

        bool jmo;
        float offx = 0.0f, offy = 0.0f;
        switch (o) {
            case 0: jmo = true; break;
            case 1: jmo = (fmodf(gx, 1.0f) < 0.5f) && (gx > 1.0f); offx = 0.5f; break;
            case 2: jmo = (fmodf(gy, 1.0f) < 0.5f) && (gy > 1.0f); offy = 0.5f; break;
            case 3: { float gxi = (float)W - gx;
                      jmo = (fmodf(gxi, 1.0f) < 0.5f) && (gxi > 1.0f); offx = -0.5f; } break;
            default:{ float gyi = (float)H - gy;
                      jmo = (fmodf(gyi, 1.0f) < 0.5f) && (gyi > 1.0f); offy = -0.5f; } break;
        }

        bool masked = jmo && m0;
        if (!masked) {
            if (lane == 0) g_cell_s[warp] = -1;
            return;
        }

        int b = (int)tg[n * 6 + 0];
        int c = (int)tg[n * 6 + 1];

        int gi = (int)truncf(gx - offx); gi = min(max(gi, 0), W - 1);
        int gj = (int)truncf(gy - offy); gj = min(max(gj, 0), H - 1);

        const float* row = pi + (size_t)((((b * NA_ + a) * H + gj) * W + gi)) * CH_;

        // class BCE across the warp
        float csum = 0.0f;
        #pragma unroll
        for (int it = 0; it < 3; it++) {
            int j = lane + it * 32;
            if (j < NC_) {
                float x = row[5 + j];
                float y = (j == c) ? 1.0f : 0.0f;
                csum += fmaxf(x, 0.0f) - x * y + log1pf(__expf(-fabsf(x)));
            }
        }
        #pragma unroll
        for (int s = 16; s; s >>= 1)
            csum += __shfl_down_sync(0xffffffffu, csum, s);

        if (lane == 0) {
            float q0 = row[0], q1 = row[1], q2 = row[2], q3 = row[3], q4 = row[4];
            float px = sigmoidf_(q0) * 2.0f - 0.5f;
            float py = sigmoidf_(q1) * 2.0f - 0.5f;
            float sw = sigmoidf_(q2) * 2.0f; float pw = sw * sw * aw;
            float sh = sigmoidf_(q3) * 2.0f; float ph = sh * sh * ah;

            float tbx = gx - (float)gi;
            float tby = gy - (float)gj;

            float iou = ciou_(px, py, pw, ph, tbx, tby, gw, gh);

            atomicAdd(&g_box[lvl], 1.0f - iou);
            atomicAdd(&g_cls[lvl], csum);
            atomicAdd(&g_nv[lvl], 1);

            int cell = woff + (((b * NA_ + a) * H + gj) * W + gi);
            atomicMax(&g_winner[cell], warp + 1);   // last-update-wins
            g_iou_s[warp]  = iou;
            g_x4_s[warp]   = q4;
            g_cell_s[warp] = cell;
        }
    } else {
        // ---------------- weighted objectness softplus sweep ----------------
        __shared__ float sh[256];
        int bid = blockIdx.x - BA;
        int tid = threadIdx.x;

        int c0 = bs * NA_ * 6400;
        int c1 = bs * NA_ * 1600;
        int c2 = bs * NA_ * 400;
        float w0 = 1.0f / (float)c0, w1 = 1.0f / (float)c1, w2 = 1.0f / (float)c2;
        int total = c0 + c1 + c2;

        float s = 0.0f;
        for (int i = bid * blockDim.x + tid; i < total; i += BOBJ * blockDim.x) {
            const float* pi; int local; float w;
            if (i < c0)            { pi = p0; local = i;            w = w0; }
            else if (i < c0 + c1)  { pi = p1; local = i - c0;       w = w1; }
            else                   { pi = p2; local = i - c0 - c1;  w = w2; }
            float x = pi[(size_t)local * CH_ + 4];
            s += w * softplus_bce0(x);
        }
        sh[tid] = s;
        __syncthreads();
        for (int st = 128; st; st >>= 1) {
            if (tid < st) sh[tid] += sh[tid + st];
            __syncthreads();
        }
        if (tid == 0) atomicAdd(&g_sp, sh[0]);
    }
}

// winner entries contribute weighted x*t correction to lobj
__global__ void k_passB(int Etot, int Elvl, float w0, float w1, float w2) {
    int e = blockIdx.x * blockDim.x + threadIdx.x;
    if (e >= Etot) return;
    int cell = g_cell_s[e];
    if (cell < 0) return;
    if (g_winner[cell] != e + 1) return;
    int lvl = e / Elvl;
    float w = (lvl == 0) ? w0 : ((lvl == 1) ? w1 : w2);
    float t = fmaxf(g_iou_s[e], 0.0f);   // obj_val = clip(iou,0)  (GR=1)
    atomicAdd(&g_corr, w * g_x4_s[e] * t);
}

__global__ void k_finalize(float* __restrict__ out, int bs) {
    float lbox = 0.0f, lcls = 0.0f;
    #pragma unroll
    for (int i = 0; i < 3; i++) {
        float nv = fmaxf((float)g_nv[i], 1.0f);
        lbox += g_box[i] / nv;
        lcls += g_cls[i] / (nv * (float)NC_);
    }
    float lobj = g_sp - g_corr;
    lbox *= 0.05f;   // BOX_GAIN
    lcls *= 0.5f;    // CLS_GAIN
    float loss = (lbox + lobj + lcls) * (float)bs;
    out[0] = loss;
    out[1] = lbox;
    out[2] = lobj;
    out[3] = lcls;
}

// ---------------- launch ----------------
extern "C" void kernel_launch(void* const* d_in, const int* in_sizes, int n_in,
                              void* d_out, int out_size) {
    const float* p0  = (const float*)d_in[0];
    const float* p1  = (const float*)d_in[1];
    const float* p2  = (const float*)d_in[2];
    const float* tg  = (const float*)d_in[3];
    const float* anc = (const float*)d_in[4];
    float* out = (float*)d_out;

    int bs = in_sizes[0] / (NA_ * 80 * 80 * CH_);
    int nt = in_sizes[3] / 6;

    int nwin = bs * NA_ * (6400 + 1600 + 400);
    int Elvl = 5 * NA_ * nt;
    int Etot = 3 * Elvl;

    k_reset<<<(nwin + 255) / 256, 256>>>(nwin);

    int BA = (Etot * 32 + 255) / 256;   // passA blocks (warp per entry)
    int BOBJ = 512;                     // objsum blocks
    k_main<<<BA + BOBJ, 256>>>(p0, p1, p2, tg, anc, nt, bs, BA, BOBJ);

    float w0 = 1.0f / (float)(bs * NA_ * 6400);
    float w1 = 1.0f / (float)(bs * NA_ * 1600);
    float w2 = 1.0f / (float)(bs * NA_ * 400);
    k_passB<<<(Etot + 255) / 256, 256>>>(Etot, Elvl, w0, w1, w2);

    k_finalize<<<1, 1>>>(out, bs);
}